// round 7
// baseline (speedup 1.0000x reference)
#include <cuda_runtime.h>

#define BB 8
#define LL 512
#define KK 512
#define MM 64
#define NN 64
#define PDIM 64
#define DD 64

// scratch (device globals; no allocations)
__device__ float g_sum8[BB * 8 * LL];             // 128 KB per-(b,ktile) partial row sums
__device__ float g_vkc [BB * KK * NN];            // 1 MB
__device__ float g_tmp8[BB * 8 * LL * NN];        // 8 MB  split-K partial (unnormalized) tmp

#define ST 68   // smem row stride (64 + 4)

// ============ K1: vkc[b,k,n] = sum_p vk[b,k,p,n] * vexp[b,k,p] ============
__global__ void __launch_bounds__(256) kv_kernel(
    const float* __restrict__ vk, const float* __restrict__ vexp) {
    __shared__ float s[256];
    int bk = blockIdx.x;
    const float* vkp = vk + (size_t)bk * PDIM * NN;
    const float* ve  = vexp + (size_t)bk * PDIM;
    int t = threadIdx.x;
    int n = t & 63, pg = t >> 6;            // 4 p-groups of 16
    float acc = 0.f;
#pragma unroll
    for (int i = 0; i < 16; i++) {
        int p = pg * 16 + i;
        acc += vkp[p * NN + n] * ve[p];
    }
    s[t] = acc;
    __syncthreads();
    if (pg == 0)
        g_vkc[(size_t)bk * NN + n] = s[n] + s[64 + n] + s[128 + n] + s[192 + n];
}

// ============ K2: fused scores + exp + (E^T @ vkc) chunk, split-K ============
// block = (b, l0: 64 rows, kt: 64 keys). smem: bufA(k tile -> vkc tile),
// bufB(qT -> Es), ssum. No g_ssT: E lives in registers + smem only.
__global__ void __launch_bounds__(256) ks_kernel(
    const float* __restrict__ q, const float* __restrict__ k,
    const float* __restrict__ scale_p) {
    extern __shared__ float s[];
    float* bufA = s;                 // [64][ST]: k tile, then vkc chunk
    float* bufB = s + 64 * ST;       // [64][ST]: qT,    then Es ([k][l])
    float* ssum = bufB + 64 * ST;    // [64]
    int t = threadIdx.x;
    int bid = blockIdx.x;
    int b  = bid >> 6;
    int r  = bid & 63;
    int l0 = (r >> 3) * 64;
    int kt = r & 7;
    int k0 = kt * 64;

    // ---- load k tile [64][64] coalesced ----
#pragma unroll
    for (int j = 0; j < 4; j++) {
        int v = t + j * 256;
        int row = v >> 4, c4 = v & 15;
        float4 x = *(const float4*)&k[((size_t)(b * KK + k0 + row)) * DD + c4 * 4];
        *(float4*)&bufA[row * ST + c4 * 4] = x;
    }
    // ---- transpose q tile 64x64 -> bufB[d][l] ----
#pragma unroll
    for (int i = 0; i < 4; i++) {
        int l = (t >> 4) + 16 * i;
        int d4 = t & 15;
        float4 x = *(const float4*)&q[((size_t)(b * LL + l0 + l)) * DD + d4 * 4];
        bufB[(d4 * 4 + 0) * ST + l] = x.x;
        bufB[(d4 * 4 + 1) * ST + l] = x.y;
        bufB[(d4 * 4 + 2) * ST + l] = x.z;
        bufB[(d4 * 4 + 3) * ST + l] = x.w;
    }
    if (t < 64) ssum[t] = 0.f;
    __syncthreads();

    // ---- scores: 4k x 4l per thread ----
    int tkg = t >> 4;          // 16 k-groups of 4
    int tlg = t & 15;          // 16 l-groups of 4
    float acc[4][4];
#pragma unroll
    for (int a = 0; a < 4; a++)
#pragma unroll
        for (int b2 = 0; b2 < 4; b2++) acc[a][b2] = 0.f;

#pragma unroll 2
    for (int d0 = 0; d0 < DD; d0 += 4) {
        float4 kv[4];
#pragma unroll
        for (int ki = 0; ki < 4; ki++)
            kv[ki] = *(float4*)&bufA[(tkg * 4 + ki) * ST + d0];
#pragma unroll
        for (int dd = 0; dd < 4; dd++) {
            float4 qa = *(float4*)&bufB[(d0 + dd) * ST + tlg * 4];
            float kd0 = ((float*)&kv[0])[dd];
            float kd1 = ((float*)&kv[1])[dd];
            float kd2 = ((float*)&kv[2])[dd];
            float kd3 = ((float*)&kv[3])[dd];
            acc[0][0] += kd0 * qa.x; acc[0][1] += kd0 * qa.y; acc[0][2] += kd0 * qa.z; acc[0][3] += kd0 * qa.w;
            acc[1][0] += kd1 * qa.x; acc[1][1] += kd1 * qa.y; acc[1][2] += kd1 * qa.z; acc[1][3] += kd1 * qa.w;
            acc[2][0] += kd2 * qa.x; acc[2][1] += kd2 * qa.y; acc[2][2] += kd2 * qa.z; acc[2][3] += kd2 * qa.w;
            acc[3][0] += kd3 * qa.x; acc[3][1] += kd3 * qa.y; acc[3][2] += kd3 * qa.z; acc[3][3] += kd3 * qa.w;
        }
    }
    __syncthreads();   // everyone done reading bufA/bufB; safe to overwrite

    // ---- exp + row-sum partials; Es -> bufB, vkc chunk -> bufA ----
    float scale = *scale_p;
    float sacc[4] = {0.f, 0.f, 0.f, 0.f};
#pragma unroll
    for (int ki = 0; ki < 4; ki++) {
        float4 e0;
        e0.x = __expf(acc[ki][0] * scale);
        e0.y = __expf(acc[ki][1] * scale);
        e0.z = __expf(acc[ki][2] * scale);
        e0.w = __expf(acc[ki][3] * scale);
        sacc[0] += e0.x; sacc[1] += e0.y; sacc[2] += e0.z; sacc[3] += e0.w;
        *(float4*)&bufB[(tkg * 4 + ki) * ST + tlg * 4] = e0;   // Es[k][l]
    }
#pragma unroll
    for (int j = 0; j < 4; j++) atomicAdd(&ssum[tlg * 4 + j], sacc[j]);
    // vkc chunk [64][64] into bufA
#pragma unroll
    for (int j = 0; j < 4; j++) {
        int v = t + j * 256;
        int row = v >> 4, c4 = v & 15;
        float4 x = *(const float4*)&g_vkc[((size_t)(b * KK + k0 + row)) * NN + c4 * 4];
        *(float4*)&bufA[row * ST + c4 * 4] = x;
    }
    __syncthreads();
    if (t < 64) g_sum8[((size_t)(b * 8 + kt)) * LL + l0 + t] = ssum[t];

    // ---- tmp_partial[l][n] = sum_k Es[k][l] * vkc[k][n]; 4l x 4n per thread ----
    int tl = t & 15;           // l group
    int tn = t >> 4;           // n group
    float acc2[4][4];
#pragma unroll
    for (int a = 0; a < 4; a++)
#pragma unroll
        for (int b2 = 0; b2 < 4; b2++) acc2[a][b2] = 0.f;
#pragma unroll 4
    for (int kk = 0; kk < 64; kk++) {
        float4 e4 = *(float4*)&bufB[kk * ST + tl * 4];
        float4 v4 = *(float4*)&bufA[kk * ST + tn * 4];
        float ee[4] = {e4.x, e4.y, e4.z, e4.w};
        float vv[4] = {v4.x, v4.y, v4.z, v4.w};
#pragma unroll
        for (int li = 0; li < 4; li++)
#pragma unroll
            for (int nj = 0; nj < 4; nj++)
                acc2[li][nj] += ee[li] * vv[nj];
    }
#pragma unroll
    for (int li = 0; li < 4; li++) {
        int l = l0 + tl * 4 + li;
        float4 o = {acc2[li][0], acc2[li][1], acc2[li][2], acc2[li][3]};
        *(float4*)&g_tmp8[(((size_t)(b * 8 + kt)) * LL + l) * NN + tn * 4] = o;
    }
}

// ============ K3: attn = vq @ tmp (combined+normalized), residual + LN ============
__global__ void __launch_bounds__(256) k3_kernel(
    const float* __restrict__ q, const float* __restrict__ vq,
    const float* __restrict__ gamma, const float* __restrict__ beta,
    float* __restrict__ out) {
    int bl = blockIdx.x;             // b*512 + l
    int b = bl >> 9, l = bl & 511;
    __shared__ __align__(16) float stmp[64];
    __shared__ float sq[64];
    __shared__ float so[64];
    __shared__ float rs[8], rq[8];
    int t = threadIdx.x;
    if (t < 64) {
        float ssum = 0.f;
        float v = 0.f;
#pragma unroll
        for (int i = 0; i < 8; i++) {
            ssum += g_sum8[((size_t)(b * 8 + i)) * LL + l];
            v    += g_tmp8[(((size_t)(b * 8 + i)) * LL + l) * NN + t];
        }
        stmp[t] = v / ssum;
        sq[t]   = q[(size_t)bl * DD + t];
    }
    __syncthreads();

    int n4 = t & 15;
    float4 tm = ((float4*)stmp)[n4];
    const float4* vq4 = (const float4*)(vq + (size_t)bl * MM * NN);
    float p[4];
#pragma unroll
    for (int i = 0; i < 4; i++) {
        float4 v = vq4[t + i * 256];         // m = (t>>4) + 16*i, n-chunk = n4
        p[i] = v.x * tm.x + v.y * tm.y + v.z * tm.z + v.w * tm.w;
    }
#pragma unroll
    for (int o = 8; o; o >>= 1)
#pragma unroll
        for (int i = 0; i < 4; i++)
            p[i] += __shfl_down_sync(0xFFFFFFFFu, p[i], o, 16);
    if ((t & 15) == 0) {
        int g = t >> 4;
#pragma unroll
        for (int i = 0; i < 4; i++) so[g + 16 * i] = p[i];
    }
    __syncthreads();

    int m = t & 63;
    float x = sq[m] + so[m];                 // residual (M == D)
    float s1 = x, s2 = x * x;
#pragma unroll
    for (int o = 16; o; o >>= 1) {
        s1 += __shfl_xor_sync(0xFFFFFFFFu, s1, o);
        s2 += __shfl_xor_sync(0xFFFFFFFFu, s2, o);
    }
    int lane = t & 31, w = t >> 5;
    if (lane == 0) { rs[w] = s1; rq[w] = s2; }
    __syncthreads();
    float a = 0.f, b2 = 0.f;
#pragma unroll
    for (int i = 0; i < 8; i++) { a += rs[i]; b2 += rq[i]; }
    float mu   = a * (1.f / 256.f);          // each m replicated 4x -> exact mean
    float var  = b2 * (1.f / 256.f) - mu * mu;
    float rstd = rsqrtf(var + 1e-3f);
    if (t < 64)
        out[(size_t)bl * MM + m] = (x - mu) * rstd * gamma[m] + beta[m];
}

extern "C" void kernel_launch(void* const* d_in, const int* in_sizes, int n_in,
                              void* d_out, int out_size) {
    const float* q     = (const float*)d_in[0];
    const float* k     = (const float*)d_in[1];
    const float* vq    = (const float*)d_in[2];
    const float* vk    = (const float*)d_in[3];
    const float* vexp  = (const float*)d_in[4];
    const float* scale = (const float*)d_in[5];
    const float* gamma = (const float*)d_in[6];
    const float* beta  = (const float*)d_in[7];
    float* out = (float*)d_out;

    kv_kernel<<<BB * KK, 256>>>(vk, vexp);

    int smemS = (64 * ST + 64 * ST + 64) * (int)sizeof(float);
    cudaFuncSetAttribute(ks_kernel, cudaFuncAttributeMaxDynamicSharedMemorySize, smemS);
    ks_kernel<<<512, 256, smemS>>>(q, k, scale);

    k3_kernel<<<BB * LL, 256>>>(q, vq, gamma, beta, out);
}

// round 8
// speedup vs baseline: 1.0237x; 1.0237x over previous
#include <cuda_runtime.h>

#define BB 8
#define LL 512
#define KK 512
#define MM 64
#define NN 64
#define PDIM 64
#define DD 64

// scratch (device globals; no allocations)
__device__ float g_sum4[BB * 4 * LL];             // 64 KB per-(b,ktile) partial row sums
__device__ float g_vkc [BB * KK * NN];            // 1 MB
__device__ float g_tmp4[BB * 4 * LL * NN];        // 4 MB split-K partial (unnormalized) tmp

// ============ K1: vkc[b,k,n] = sum_p vk[b,k,p,n] * vexp[b,k,p] ============
// 4 bk-slabs per block, float4 loads (LDG.128), vexp via smem.
__global__ void __launch_bounds__(256) kv_kernel(
    const float* __restrict__ vk, const float* __restrict__ vexp) {
    __shared__ float sve[256];
    __shared__ __align__(16) float4 red[256];
    int t = threadIdx.x;
    int bk0 = blockIdx.x * 4;

    // stage vexp for 4 slabs (256 floats)
    sve[t] = vexp[(size_t)bk0 * PDIM + t];
    __syncthreads();

    int slab = t >> 6;
    int tt = t & 63;
    int n4 = tt & 15;          // float4 column
    int pg = tt >> 4;          // 4 p-groups of 16
    const float4* vk4 = (const float4*)(vk + (size_t)(bk0 + slab) * PDIM * NN);
    const float* ve = &sve[slab * 64];
    float4 acc = make_float4(0.f, 0.f, 0.f, 0.f);
#pragma unroll
    for (int i = 0; i < 16; i++) {
        int p = pg * 16 + i;
        float4 a = vk4[p * 16 + n4];
        float e = ve[p];
        acc.x += a.x * e; acc.y += a.y * e; acc.z += a.z * e; acc.w += a.w * e;
    }
    red[t] = acc;
    __syncthreads();
    if (tt < 16) {
        float4 r0 = red[slab * 64 + n4];
        float4 r1 = red[slab * 64 + 16 + n4];
        float4 r2 = red[slab * 64 + 32 + n4];
        float4 r3 = red[slab * 64 + 48 + n4];
        float4 o = make_float4(r0.x + r1.x + r2.x + r3.x, r0.y + r1.y + r2.y + r3.y,
                               r0.z + r1.z + r2.z + r3.z, r0.w + r1.w + r2.w + r3.w);
        *(float4*)&g_vkc[(size_t)(bk0 + slab) * NN + n4 * 4] = o;
    }
}

// ============ K2: fused scores(128x128) + exp + (E @ vkc), split-K ============
// smem: kb[128][68] (k tile -> vkc chunk) | qT[64][132] | Es[128][132] | ssum[128]
#define KBS 68
#define QTS 132
#define ESS 132
#define OFF_QT  (128 * KBS)
#define OFF_ES  (OFF_QT + 64 * QTS)
#define OFF_SS  (OFF_ES + 128 * ESS)
#define SMEM_KS (OFF_SS + 128)

__global__ void __launch_bounds__(256) ks_kernel(
    const float* __restrict__ q, const float* __restrict__ k,
    const float* __restrict__ scale_p) {
    extern __shared__ float s[];
    float* kb   = s;               // [128][KBS]
    float* qT   = s + OFF_QT;      // [64][QTS]   qT[d][l]
    float* Es   = s + OFF_ES;      // [128][ESS]  Es[k][l]
    float* ssum = s + OFF_SS;      // [128]
    int t = threadIdx.x;
    int bid = blockIdx.x;
    int b  = bid >> 4;
    int r  = bid & 15;
    int l0 = (r >> 2) * 128;
    int kt = r & 3;
    int k0 = kt * 128;

    // load k tile [128][64]
#pragma unroll
    for (int j = 0; j < 8; j++) {
        int v = t + j * 256;
        int row = v >> 4, c4 = v & 15;
        float4 x = *(const float4*)&k[((size_t)(b * KK + k0 + row)) * DD + c4 * 4];
        *(float4*)&kb[row * KBS + c4 * 4] = x;
    }
    // transpose q tile [128 l][64 d] -> qT[d][l]
#pragma unroll
    for (int j = 0; j < 8; j++) {
        int v = t + j * 256;
        int l = v >> 4, d4 = v & 15;
        float4 x = *(const float4*)&q[((size_t)(b * LL + l0 + l)) * DD + d4 * 4];
        qT[(d4 * 4 + 0) * QTS + l] = x.x;
        qT[(d4 * 4 + 1) * QTS + l] = x.y;
        qT[(d4 * 4 + 2) * QTS + l] = x.z;
        qT[(d4 * 4 + 3) * QTS + l] = x.w;
    }
    if (t < 128) ssum[t] = 0.f;
    __syncthreads();

    // ---- GEMM1: scores 8k x 8l per thread ----
    int tkg = t >> 4;      // 16 k-groups of 8
    int tlg = t & 15;      // 16 l-groups of 8
    float acc[8][8];
#pragma unroll
    for (int a = 0; a < 8; a++)
#pragma unroll
        for (int c = 0; c < 8; c++) acc[a][c] = 0.f;

    for (int d0 = 0; d0 < DD; d0 += 4) {
        float4 kv[8];
#pragma unroll
        for (int ki = 0; ki < 8; ki++)
            kv[ki] = *(float4*)&kb[(tkg * 8 + ki) * KBS + d0];
#pragma unroll
        for (int dd = 0; dd < 4; dd++) {
            float4 qa = *(float4*)&qT[(d0 + dd) * QTS + tlg * 8];
            float4 qb = *(float4*)&qT[(d0 + dd) * QTS + tlg * 8 + 4];
            float ql[8] = {qa.x, qa.y, qa.z, qa.w, qb.x, qb.y, qb.z, qb.w};
#pragma unroll
            for (int ki = 0; ki < 8; ki++) {
                float kd = ((float*)&kv[ki])[dd];
#pragma unroll
                for (int lj = 0; lj < 8; lj++) acc[ki][lj] += kd * ql[lj];
            }
        }
    }
    __syncthreads();   // all GEMM1 reads of kb/qT done

    // ---- exp -> Es, row-sum partials; vkc chunk -> kb ----
    float scale = *scale_p;
    float sacc[8];
#pragma unroll
    for (int j = 0; j < 8; j++) sacc[j] = 0.f;
#pragma unroll
    for (int ki = 0; ki < 8; ki++) {
        float4 e0, e1;
        e0.x = __expf(acc[ki][0] * scale);
        e0.y = __expf(acc[ki][1] * scale);
        e0.z = __expf(acc[ki][2] * scale);
        e0.w = __expf(acc[ki][3] * scale);
        e1.x = __expf(acc[ki][4] * scale);
        e1.y = __expf(acc[ki][5] * scale);
        e1.z = __expf(acc[ki][6] * scale);
        e1.w = __expf(acc[ki][7] * scale);
        sacc[0] += e0.x; sacc[1] += e0.y; sacc[2] += e0.z; sacc[3] += e0.w;
        sacc[4] += e1.x; sacc[5] += e1.y; sacc[6] += e1.z; sacc[7] += e1.w;
        *(float4*)&Es[(tkg * 8 + ki) * ESS + tlg * 8]     = e0;
        *(float4*)&Es[(tkg * 8 + ki) * ESS + tlg * 8 + 4] = e1;
    }
#pragma unroll
    for (int j = 0; j < 8; j++) atomicAdd(&ssum[tlg * 8 + j], sacc[j]);
    // vkc chunk [128][64] into kb
#pragma unroll
    for (int j = 0; j < 8; j++) {
        int v = t + j * 256;
        int row = v >> 4, c4 = v & 15;
        float4 x = *(const float4*)&g_vkc[((size_t)(b * KK + k0 + row)) * NN + c4 * 4];
        *(float4*)&kb[row * KBS + c4 * 4] = x;
    }
    __syncthreads();
    if (t < 128) g_sum4[((size_t)(b * 4 + kt)) * LL + l0 + t] = ssum[t];

    // ---- GEMM2: tmp_partial[l][n] = sum_k Es[k][l]*vkc[k][n]; 8l x 4n ----
    int tl = t & 15;       // l-group of 8
    int tn = t >> 4;       // n-group of 4
    float acc2[8][4];
#pragma unroll
    for (int a = 0; a < 8; a++)
#pragma unroll
        for (int c = 0; c < 4; c++) acc2[a][c] = 0.f;
#pragma unroll 2
    for (int kk = 0; kk < 128; kk++) {
        float4 ea = *(float4*)&Es[kk * ESS + tl * 8];
        float4 eb = *(float4*)&Es[kk * ESS + tl * 8 + 4];
        float4 v4 = *(float4*)&kb[kk * KBS + tn * 4];
        float ee[8] = {ea.x, ea.y, ea.z, ea.w, eb.x, eb.y, eb.z, eb.w};
        float vv[4] = {v4.x, v4.y, v4.z, v4.w};
#pragma unroll
        for (int li = 0; li < 8; li++)
#pragma unroll
            for (int nj = 0; nj < 4; nj++)
                acc2[li][nj] += ee[li] * vv[nj];
    }
#pragma unroll
    for (int li = 0; li < 8; li++) {
        int l = l0 + tl * 8 + li;
        float4 o = {acc2[li][0], acc2[li][1], acc2[li][2], acc2[li][3]};
        *(float4*)&g_tmp4[(((size_t)(b * 4 + kt)) * LL + l) * NN + tn * 4] = o;
    }
}

// ============ K3: attn = vq @ tmp (combined+normalized), residual + LN ============
__global__ void __launch_bounds__(256) k3_kernel(
    const float* __restrict__ q, const float* __restrict__ vq,
    const float* __restrict__ gamma, const float* __restrict__ beta,
    float* __restrict__ out) {
    int bl = blockIdx.x;             // b*512 + l
    int b = bl >> 9, l = bl & 511;
    __shared__ __align__(16) float stmp[64];
    __shared__ float sq[64];
    __shared__ float so[64];
    __shared__ float rs[8], rq[8];
    int t = threadIdx.x;
    if (t < 64) {
        float ssum = 0.f;
        float v = 0.f;
#pragma unroll
        for (int i = 0; i < 4; i++) {
            ssum += g_sum4[((size_t)(b * 4 + i)) * LL + l];
            v    += g_tmp4[(((size_t)(b * 4 + i)) * LL + l) * NN + t];
        }
        stmp[t] = v / ssum;
        sq[t]   = q[(size_t)bl * DD + t];
    }
    __syncthreads();

    int n4 = t & 15;
    float4 tm = ((float4*)stmp)[n4];
    const float4* vq4 = (const float4*)(vq + (size_t)bl * MM * NN);
    float p[4];
#pragma unroll
    for (int i = 0; i < 4; i++) {
        float4 v = vq4[t + i * 256];         // m = (t>>4) + 16*i, n-chunk = n4
        p[i] = v.x * tm.x + v.y * tm.y + v.z * tm.z + v.w * tm.w;
    }
#pragma unroll
    for (int o = 8; o; o >>= 1)
#pragma unroll
        for (int i = 0; i < 4; i++)
            p[i] += __shfl_down_sync(0xFFFFFFFFu, p[i], o, 16);
    if ((t & 15) == 0) {
        int g = t >> 4;
#pragma unroll
        for (int i = 0; i < 4; i++) so[g + 16 * i] = p[i];
    }
    __syncthreads();

    int m = t & 63;
    float x = sq[m] + so[m];                 // residual (M == D)
    float s1 = x, s2 = x * x;
#pragma unroll
    for (int o = 16; o; o >>= 1) {
        s1 += __shfl_xor_sync(0xFFFFFFFFu, s1, o);
        s2 += __shfl_xor_sync(0xFFFFFFFFu, s2, o);
    }
    int lane = t & 31, w = t >> 5;
    if (lane == 0) { rs[w] = s1; rq[w] = s2; }
    __syncthreads();
    float a = 0.f, b2 = 0.f;
#pragma unroll
    for (int i = 0; i < 8; i++) { a += rs[i]; b2 += rq[i]; }
    float mu   = a * (1.f / 256.f);          // each m replicated 4x -> exact mean
    float var  = b2 * (1.f / 256.f) - mu * mu;
    float rstd = rsqrtf(var + 1e-3f);
    if (t < 64)
        out[(size_t)bl * MM + m] = (x - mu) * rstd * gamma[m] + beta[m];
}

extern "C" void kernel_launch(void* const* d_in, const int* in_sizes, int n_in,
                              void* d_out, int out_size) {
    const float* q     = (const float*)d_in[0];
    const float* k     = (const float*)d_in[1];
    const float* vq    = (const float*)d_in[2];
    const float* vk    = (const float*)d_in[3];
    const float* vexp  = (const float*)d_in[4];
    const float* scale = (const float*)d_in[5];
    const float* gamma = (const float*)d_in[6];
    const float* beta  = (const float*)d_in[7];
    float* out = (float*)d_out;

    kv_kernel<<<BB * KK / 4, 256>>>(vk, vexp);

    int smemS = SMEM_KS * (int)sizeof(float);
    cudaFuncSetAttribute(ks_kernel, cudaFuncAttributeMaxDynamicSharedMemorySize, smemS);
    ks_kernel<<<128, 256, smemS>>>(q, k, scale);

    k3_kernel<<<BB * LL, 256>>>(q, vq, gamma, beta, out);
}